// round 7
// baseline (speedup 1.0000x reference)
#include <cuda_runtime.h>
#include <cstdint>

// trans_b: [32, 64, 256, 256] fp32 = 32 batches x 64 planes x 16384 float4
#define NBATCH     32
#define NBLOCKS    512
#define NTHREADS   512
#define UNIT_F4    4096u            // 64 KB units (quarter plane)
#define TOTAL_U    8192u            // 2048 planes * 4
#define UNITS_PB   256u             // units per batch
#define W_UNITS    768u             // pool may lead scale claims by 3 batches (~50 MB)

__device__ float    g_partial[TOTAL_U];
__device__ float    g_scale[2048];
__device__ unsigned g_pticket;        // pool units claimed
__device__ unsigned g_sclaim;         // scale units claimed (CAS, bounded)
__device__ unsigned g_nready;         // batches with scale published
__device__ unsigned g_pdone[NBATCH];  // pool units finished per batch
__device__ unsigned g_ready[NBATCH];
__device__ unsigned g_cnt, g_gen;     // entry barrier (replay-safe)

__device__ __forceinline__ void entry_barrier()
{
    __syncthreads();
    if (threadIdx.x == 0) {
        unsigned gen = atomicAdd(&g_gen, 0u);
        if (atomicAdd(&g_cnt, 1u) == NBLOCKS - 1u) {
            atomicExch(&g_cnt, 0u);
            __threadfence();
            atomicAdd(&g_gen, 1u);
        } else {
            while (atomicAdd(&g_gen, 0u) == gen) __nanosleep(32);
        }
        __threadfence();
    }
    __syncthreads();
}

__global__ void __launch_bounds__(NTHREADS, 4) se_pipeline_kernel(
    const float* __restrict__ x, float* __restrict__ y,
    const float* __restrict__ w_down,  // [4,64]
    const float* __restrict__ b_down,  // [4]
    const float* __restrict__ w_up,    // [64,4]
    const float* __restrict__ b_up)    // [64]
{
    const int tid = threadIdx.x;
    const float4* __restrict__ px = reinterpret_cast<const float4*>(x);
    float4*       __restrict__ py = reinterpret_cast<float4*>(y);

    __shared__ float    sred[16];
    __shared__ float    sp[64];
    __shared__ float    sh[4];
    __shared__ unsigned s_u;
    __shared__ int      s_kind;       // 0=pool 1=scale 2=exit
    __shared__ int      s_last;

    // Per-launch counter resets (block 0), published via entry barrier.
    if (blockIdx.x == 0) {
        if (tid == 0) { g_pticket = 0u; g_sclaim = 0u; g_nready = 0u; }
        if (tid < NBATCH) { g_pdone[tid] = 0u; g_ready[tid] = 0u; }
        __threadfence();
    }
    entry_barrier();

    for (;;) {
        // ----------------- work selection (tid 0, ~3 atomics) -------------
        if (tid == 0) {
            int kind = -1; unsigned u = 0;
            while (kind < 0) {
                const unsigned bound = atomicAdd(&g_nready, 0u) << 8;
                unsigned sc = atomicAdd(&g_sclaim, 0u);
                while (sc < bound) {                   // bounded CAS claim
                    unsigned old = atomicCAS(&g_sclaim, sc, sc + 1u);
                    if (old == sc) { u = sc; kind = 1; break; }
                    sc = old;
                }
                if (kind >= 0) break;
                if (sc >= TOTAL_U) { kind = 2; break; }   // all scale claimed
                const unsigned pt = atomicAdd(&g_pticket, 0u);
                if (pt < TOTAL_U && pt < sc + W_UNITS) {  // windowed pool
                    unsigned p = atomicAdd(&g_pticket, 1u);
                    if (p < TOTAL_U) { u = p; kind = 0; break; }
                } else {
                    __nanosleep(64);
                }
            }
            if (kind == 1) {                           // batch must be ready
                const unsigned b = u >> 8;
                while (atomicAdd(&g_ready[b], 0u) == 0u) __nanosleep(32);
                __threadfence();                       // acquire g_scale[b]
            }
            s_u = u; s_kind = kind;
        }
        __syncthreads();
        const unsigned u = s_u;
        const int kind = s_kind;
        __syncthreads();

        if (kind == 2) break;

        if (kind == 0) {
            // ----------------- pool one 64 KB quarter-plane ---------------
            const size_t base = (size_t)u << 12;
            float a0 = 0.0f, a1 = 0.0f;
            #pragma unroll
            for (int i = 0; i < 8; i += 2) {
                float4 v = __ldcg(px + base + tid + (size_t)i * NTHREADS);
                float4 w = __ldcg(px + base + tid + (size_t)(i + 1) * NTHREADS);
                a0 += (v.x + v.y) + (v.z + v.w);
                a1 += (w.x + w.y) + (w.z + w.w);
            }
            float sum = a0 + a1;
            #pragma unroll
            for (int o = 16; o > 0; o >>= 1)
                sum += __shfl_xor_sync(0xFFFFFFFFu, sum, o);
            if ((tid & 31) == 0) sred[tid >> 5] = sum;
            __syncthreads();
            if (tid == 0) {
                float t = 0.0f;
                #pragma unroll
                for (int j = 0; j < 16; j++) t += sred[j];
                __stcg(&g_partial[u], t);
                __threadfence();
                unsigned old = atomicAdd(&g_pdone[u >> 8], 1u);
                s_last = (old == UNITS_PB - 1u);
            }
            __syncthreads();

            if (s_last) {
                // Batch b fully pooled by this block's unit: inline MLP.
                const int b = (int)(u >> 8);
                if (tid == 0) __threadfence();
                __syncthreads();
                if (tid < 64) {
                    const float* pp = g_partial + ((size_t)(b * 64 + tid) << 2);
                    sp[tid] = ((__ldcg(pp + 0) + __ldcg(pp + 1)) +
                               (__ldcg(pp + 2) + __ldcg(pp + 3))) * (1.0f / 65536.0f);
                }
                __syncthreads();
                if (tid < 4) {
                    float h = b_down[tid];
                    #pragma unroll 8
                    for (int k = 0; k < 64; k++)
                        h = fmaf(sp[k], __ldg(&w_down[tid * 64 + k]), h);
                    sh[tid] = fmaxf(h, 0.0f);
                }
                __syncthreads();
                if (tid < 64) {
                    float s = b_up[tid];
                    #pragma unroll
                    for (int m = 0; m < 4; m++)
                        s = fmaf(sh[m], __ldg(&w_up[tid * 4 + m]), s);
                    __stcg(&g_scale[b * 64 + tid], 1.0f / (1.0f + expf(-s)));
                    __threadfence();
                }
                __syncthreads();
                if (tid == 0) {
                    atomicExch(&g_ready[b], 1u);       // publish flag first
                    atomicAdd(&g_nready, 1u);          // then raise claim bound
                }
            }
        } else {
            // ----------------- scale one 64 KB quarter-plane --------------
            const size_t base = (size_t)u << 12;
            const float s = __ldcg(&g_scale[u >> 2]);
            #pragma unroll
            for (int i = 0; i < 8; i++) {
                const size_t idx = base + tid + (size_t)i * NTHREADS;
                float4 v = __ldcg(px + idx);           // L2 hit: pooled <=3 batches ago
                v.x *= s; v.y *= s; v.z *= s; v.w *= s;
                __stcs(py + idx, v);                   // evict-first stores
            }
        }
    }
}

extern "C" void kernel_launch(void* const* d_in, const int* in_sizes, int n_in,
                              void* d_out, int out_size)
{
    const float* trans_b = (const float*)d_in[0];
    const float* w_down  = (const float*)d_in[1];
    const float* b_down  = (const float*)d_in[2];
    const float* w_up    = (const float*)d_in[3];
    const float* b_up    = (const float*)d_in[4];
    float* out = (float*)d_out;

    se_pipeline_kernel<<<NBLOCKS, NTHREADS>>>(trans_b, out, w_down, b_down, w_up, b_up);
}

// round 8
// speedup vs baseline: 6.6518x; 6.6518x over previous
#include <cuda_runtime.h>
#include <cstdint>

// trans_b: [32, 64, 256, 256] fp32 = 32 batches x 64 planes x 16384 float4
#define NBATCH    32
#define NBLOCKS   512
#define NTHREADS  512
#define UNIT_F4   4096u       // 64 KB unit (quarter plane); 8 f4 per thread
#define TOTAL_U   8192u       // 2048 planes * 4
#define UNITS_PB  256u        // units per batch
#define ITERS     16          // TOTAL_U / NBLOCKS
#define LEAD      2           // scale trails pool by 2 iters (64 MB L2 lag)

__device__ float             g_partial[TOTAL_U];
__device__ float             g_scale[2048];
__device__ unsigned          g_pdone[NBATCH];   // pool units finished per batch
__device__ volatile unsigned g_ready[NBATCH];   // scale published flags
__device__ unsigned          g_cnt, g_gen;      // entry barrier (replay-safe)

__device__ __forceinline__ void entry_barrier()
{
    __syncthreads();
    if (threadIdx.x == 0) {
        unsigned gen = atomicAdd(&g_gen, 0u);
        if (atomicAdd(&g_cnt, 1u) == NBLOCKS - 1u) {
            atomicExch(&g_cnt, 0u);
            __threadfence();
            atomicAdd(&g_gen, 1u);
        } else {
            while (atomicAdd(&g_gen, 0u) == gen) __nanosleep(32);
        }
        __threadfence();
    }
    __syncthreads();
}

__global__ void __launch_bounds__(NTHREADS, 4) se_static_pipeline(
    const float* __restrict__ x, float* __restrict__ y,
    const float* __restrict__ w_down,  // [4,64]
    const float* __restrict__ b_down,  // [4]
    const float* __restrict__ w_up,    // [64,4]
    const float* __restrict__ b_up)    // [64]
{
    const int tid = threadIdx.x;
    const int bid = blockIdx.x;
    const float4* __restrict__ px = reinterpret_cast<const float4*>(x);
    float4*       __restrict__ py = reinterpret_cast<float4*>(y);

    __shared__ float sred[16];
    __shared__ float sp[64];
    __shared__ float sh[4];
    __shared__ int   s_last;

    // Per-launch flag resets (block 0), published via entry barrier.
    if (bid == 0) {
        if (tid < NBATCH) { g_pdone[tid] = 0u; g_ready[tid] = 0u; }
        __threadfence();
    }
    entry_barrier();

    for (int t = 0; t < ITERS + LEAD; t++) {
        // ---------------- POOL: unit t*512 + bid (t < ITERS) --------------
        if (t < ITERS) {
            const unsigned u = (unsigned)t * NBLOCKS + bid;
            const size_t base = (size_t)u << 12;
            float a0 = 0.0f, a1 = 0.0f;
            #pragma unroll
            for (int i = 0; i < 8; i += 2) {
                float4 v = __ldcg(px + base + tid + (size_t)i * NTHREADS);
                float4 w = __ldcg(px + base + tid + (size_t)(i + 1) * NTHREADS);
                a0 += (v.x + v.y) + (v.z + v.w);
                a1 += (w.x + w.y) + (w.z + w.w);
            }
            float sum = a0 + a1;
            #pragma unroll
            for (int o = 16; o > 0; o >>= 1)
                sum += __shfl_xor_sync(0xFFFFFFFFu, sum, o);
            if ((tid & 31) == 0) sred[tid >> 5] = sum;
            __syncthreads();
            if (tid == 0) {
                float tt = 0.0f;
                #pragma unroll
                for (int j = 0; j < 16; j++) tt += sred[j];
                __stcg(&g_partial[u], tt);
                __threadfence();
                unsigned old = atomicAdd(&g_pdone[u >> 8], 1u);
                s_last = (old == UNITS_PB - 1u);
            }
            __syncthreads();

            if (s_last) {
                // This block finished batch b's last pool unit: inline MLP.
                const int b = (int)(u >> 8);
                if (tid == 0) __threadfence();           // see all partials
                __syncthreads();
                if (tid < 64) {
                    const float* pp = g_partial + ((size_t)(b * 64 + tid) << 2);
                    sp[tid] = ((__ldcg(pp + 0) + __ldcg(pp + 1)) +
                               (__ldcg(pp + 2) + __ldcg(pp + 3))) * (1.0f / 65536.0f);
                }
                __syncthreads();
                if (tid < 4) {
                    float h = b_down[tid];
                    #pragma unroll 8
                    for (int k = 0; k < 64; k++)
                        h = fmaf(sp[k], __ldg(&w_down[tid * 64 + k]), h);
                    sh[tid] = fmaxf(h, 0.0f);
                }
                __syncthreads();
                if (tid < 64) {
                    float s = b_up[tid];
                    #pragma unroll
                    for (int m = 0; m < 4; m++)
                        s = fmaf(sh[m], __ldg(&w_up[tid * 4 + m]), s);
                    __stcg(&g_scale[b * 64 + tid], 1.0f / (1.0f + expf(-s)));
                }
                __syncthreads();
                if (tid == 0) {
                    __threadfence();                     // release g_scale
                    g_ready[b] = 1u;                     // volatile flag store
                }
            }
        }

        // ---------------- SCALE: unit (t-LEAD)*512 + bid -------------------
        if (t >= LEAD) {
            const unsigned v = (unsigned)(t - LEAD) * NBLOCKS + bid;
            const unsigned b = v >> 8;
            if (tid == 0) {
                while (g_ready[b] == 0u) __nanosleep(64);  // read-only spin
                __threadfence();                           // acquire g_scale
            }
            __syncthreads();

            const size_t base = (size_t)v << 12;
            const float s = __ldcg(&g_scale[v >> 2]);
            #pragma unroll
            for (int i = 0; i < 8; i++) {
                const size_t idx = base + tid + (size_t)i * NTHREADS;
                float4 w = __ldcg(px + idx);       // L2 hit: pooled 2 iters ago
                w.x *= s; w.y *= s; w.z *= s; w.w *= s;
                __stcs(py + idx, w);               // evict-first stores
            }
        }
    }
}

extern "C" void kernel_launch(void* const* d_in, const int* in_sizes, int n_in,
                              void* d_out, int out_size)
{
    const float* trans_b = (const float*)d_in[0];
    const float* w_down  = (const float*)d_in[1];
    const float* b_down  = (const float*)d_in[2];
    const float* w_up    = (const float*)d_in[3];
    const float* b_up    = (const float*)d_in[4];
    float* out = (float*)d_out;

    se_static_pipeline<<<NBLOCKS, NTHREADS>>>(trans_b, out, w_down, b_down, w_up, b_up);
}

// round 9
// speedup vs baseline: 8.5698x; 1.2884x over previous
#include <cuda_runtime.h>
#include <cstdint>

// trans_b: [32, 64, 256, 256] fp32 -> 2048 planes of 16384 float4
#define NPLANES   2048
#define PLANE_F4  16384
#define TOTAL_F4  33554432            // 2048 * 16384

__device__ float g_pooled[NPLANES];
__device__ float g_scale[NPLANES];

// ---------------------------------------------------------------------------
// Kernel 1: per-plane global average pool. One block per (b,c) plane.
// Measured at 86.9% DRAM (6.88 TB/s) — at the chip's streaming ceiling.
// ---------------------------------------------------------------------------
__global__ void __launch_bounds__(256) se_pool_kernel(const float* __restrict__ x)
{
    const int plane = blockIdx.x;
    const float4* __restrict__ p =
        reinterpret_cast<const float4*>(x) + (size_t)plane * PLANE_F4;

    float sum = 0.0f;
    for (int i = threadIdx.x; i < PLANE_F4; i += 256) {
        float4 v = p[i];
        sum += (v.x + v.y) + (v.z + v.w);
    }

    #pragma unroll
    for (int o = 16; o > 0; o >>= 1)
        sum += __shfl_xor_sync(0xFFFFFFFFu, sum, o);

    __shared__ float s[8];
    const int lane = threadIdx.x & 31;
    const int w    = threadIdx.x >> 5;
    if (lane == 0) s[w] = sum;
    __syncthreads();
    if (w == 0) {
        sum = (lane < 8) ? s[lane] : 0.0f;
        #pragma unroll
        for (int o = 4; o > 0; o >>= 1)
            sum += __shfl_xor_sync(0xFFFFFFFFu, sum, o);
        if (lane == 0)
            g_pooled[plane] = sum * (1.0f / 65536.0f);
    }
}

// ---------------------------------------------------------------------------
// Kernel 2: SE MLP 64 -> 4 (relu) -> 64 (sigmoid). One block per batch.
// ---------------------------------------------------------------------------
__global__ void __launch_bounds__(64) se_mlp_kernel(
    const float* __restrict__ w_down,  // [4, 64]
    const float* __restrict__ b_down,  // [4]
    const float* __restrict__ w_up,    // [64, 4]
    const float* __restrict__ b_up)    // [64]
{
    const int b = blockIdx.x;   // 0..31
    const int c = threadIdx.x;  // 0..63

    __shared__ float pooled[64];
    __shared__ float hidden[4];

    pooled[c] = g_pooled[b * 64 + c];
    __syncthreads();

    if (c < 4) {
        float h = b_down[c];
        #pragma unroll 8
        for (int k = 0; k < 64; k++)
            h = fmaf(pooled[k], w_down[c * 64 + k], h);
        hidden[c] = fmaxf(h, 0.0f);
    }
    __syncthreads();

    float s = b_up[c];
    #pragma unroll
    for (int m = 0; m < 4; m++)
        s = fmaf(hidden[m], w_up[c * 4 + m], s);

    g_scale[b * 64 + c] = 1.0f / (1.0f + expf(-s));
}

// ---------------------------------------------------------------------------
// Kernel 3: elementwise channel rescale, TWO float4 per thread (ILP-2).
// Reverse block order harvests the pool kernel's L2 tail (small, free win).
// Streaming policies: reads and writes both have zero reuse.
// Each block covers 512 consecutive float4 (8 KB): thread t handles
// base+t and base+t+256, both fully coalesced.
// ---------------------------------------------------------------------------
__global__ void __launch_bounds__(256) se_scale_kernel(
    const float* __restrict__ x, float* __restrict__ y)
{
    const size_t chunk = (size_t)(gridDim.x - 1u - blockIdx.x);
    const size_t base  = chunk * 512 + threadIdx.x;
    const float4* __restrict__ px = reinterpret_cast<const float4*>(x);
    float4*       __restrict__ py = reinterpret_cast<float4*>(y);

    // Both halves of the 8 KB block lie in one plane (512 | 16384), so one
    // scale lookup serves both (uniform across the block -> L1-broadcast).
    const float s = g_scale[base >> 14];

    float4 v0 = __ldcs(px + base);
    float4 v1 = __ldcs(px + base + 256);
    v0.x *= s; v0.y *= s; v0.z *= s; v0.w *= s;
    v1.x *= s; v1.y *= s; v1.z *= s; v1.w *= s;
    __stcs(py + base,       v0);
    __stcs(py + base + 256, v1);
}

// ---------------------------------------------------------------------------
extern "C" void kernel_launch(void* const* d_in, const int* in_sizes, int n_in,
                              void* d_out, int out_size)
{
    const float* trans_b = (const float*)d_in[0];
    const float* w_down  = (const float*)d_in[1];
    const float* b_down  = (const float*)d_in[2];
    const float* w_up    = (const float*)d_in[3];
    const float* b_up    = (const float*)d_in[4];
    float* out = (float*)d_out;

    se_pool_kernel<<<NPLANES, 256>>>(trans_b);
    se_mlp_kernel<<<32, 64>>>(w_down, b_down, w_up, b_up);
    se_scale_kernel<<<TOTAL_F4 / 512, 256>>>(trans_b, out);
}

// round 10
// speedup vs baseline: 8.5835x; 1.0016x over previous
#include <cuda_runtime.h>
#include <cstdint>

// trans_b: [32, 64, 256, 256] fp32 -> 2048 planes of 16384 float4
#define NPLANES   2048
#define PLANE_F4  16384
#define TOTAL_F4  33554432            // 2048 * 16384

__device__ float g_pooled[NPLANES];
__device__ float g_scale[NPLANES];

// ---------------------------------------------------------------------------
// Kernel 1: per-plane global average pool. One block per (b,c) plane.
// Measured at ~85-87% DRAM (6.8-6.9 TB/s) — at the chip's streaming ceiling.
// ---------------------------------------------------------------------------
__global__ void __launch_bounds__(256) se_pool_kernel(const float* __restrict__ x)
{
    const int plane = blockIdx.x;
    const float4* __restrict__ p =
        reinterpret_cast<const float4*>(x) + (size_t)plane * PLANE_F4;

    float sum = 0.0f;
    for (int i = threadIdx.x; i < PLANE_F4; i += 256) {
        float4 v = p[i];
        sum += (v.x + v.y) + (v.z + v.w);
    }

    #pragma unroll
    for (int o = 16; o > 0; o >>= 1)
        sum += __shfl_xor_sync(0xFFFFFFFFu, sum, o);

    __shared__ float s[8];
    const int lane = threadIdx.x & 31;
    const int w    = threadIdx.x >> 5;
    if (lane == 0) s[w] = sum;
    __syncthreads();
    if (w == 0) {
        sum = (lane < 8) ? s[lane] : 0.0f;
        #pragma unroll
        for (int o = 4; o > 0; o >>= 1)
            sum += __shfl_xor_sync(0xFFFFFFFFu, sum, o);
        if (lane == 0)
            g_pooled[plane] = sum * (1.0f / 65536.0f);
    }
}

// ---------------------------------------------------------------------------
// Kernel 2: SE MLP 64 -> 4 (relu) -> 64 (sigmoid). One block per batch.
// ---------------------------------------------------------------------------
__global__ void __launch_bounds__(64) se_mlp_kernel(
    const float* __restrict__ w_down,  // [4, 64]
    const float* __restrict__ b_down,  // [4]
    const float* __restrict__ w_up,    // [64, 4]
    const float* __restrict__ b_up)    // [64]
{
    const int b = blockIdx.x;   // 0..31
    const int c = threadIdx.x;  // 0..63

    __shared__ float pooled[64];
    __shared__ float hidden[4];

    pooled[c] = g_pooled[b * 64 + c];
    __syncthreads();

    if (c < 4) {
        float h = b_down[c];
        #pragma unroll 8
        for (int k = 0; k < 64; k++)
            h = fmaf(pooled[k], w_down[c * 64 + k], h);
        hidden[c] = fmaxf(h, 0.0f);
    }
    __syncthreads();

    float s = b_up[c];
    #pragma unroll
    for (int m = 0; m < 4; m++)
        s = fmaf(hidden[m], w_up[c * 4 + m], s);

    g_scale[b * 64 + c] = 1.0f / (1.0f + expf(-s));
}

// ---------------------------------------------------------------------------
// Kernel 3: elementwise channel rescale, FOUR float4 per thread (ILP-4).
// All 4 loads issued back-to-back (front-batched -> max memory-level
// parallelism across the mixed read+write stream), then 4 streaming stores.
// Block covers 1024 consecutive float4 (16 KB); 1024 | 16384, so the whole
// block lies in one plane -> one uniform scale lookup.
// Reverse block order harvests the pool kernel's L2 tail.
// ---------------------------------------------------------------------------
__global__ void __launch_bounds__(256) se_scale_kernel(
    const float* __restrict__ x, float* __restrict__ y)
{
    const size_t chunk = (size_t)(gridDim.x - 1u - blockIdx.x);
    const size_t base  = chunk * 1024 + threadIdx.x;
    const float4* __restrict__ px = reinterpret_cast<const float4*>(x);
    float4*       __restrict__ py = reinterpret_cast<float4*>(y);

    const float s = g_scale[base >> 14];

    float4 v0 = __ldcs(px + base);
    float4 v1 = __ldcs(px + base + 256);
    float4 v2 = __ldcs(px + base + 512);
    float4 v3 = __ldcs(px + base + 768);

    v0.x *= s; v0.y *= s; v0.z *= s; v0.w *= s;
    v1.x *= s; v1.y *= s; v1.z *= s; v1.w *= s;
    v2.x *= s; v2.y *= s; v2.z *= s; v2.w *= s;
    v3.x *= s; v3.y *= s; v3.z *= s; v3.w *= s;

    __stcs(py + base,       v0);
    __stcs(py + base + 256, v1);
    __stcs(py + base + 512, v2);
    __stcs(py + base + 768, v3);
}

// ---------------------------------------------------------------------------
extern "C" void kernel_launch(void* const* d_in, const int* in_sizes, int n_in,
                              void* d_out, int out_size)
{
    const float* trans_b = (const float*)d_in[0];
    const float* w_down  = (const float*)d_in[1];
    const float* b_down  = (const float*)d_in[2];
    const float* w_up    = (const float*)d_in[3];
    const float* b_up    = (const float*)d_in[4];
    float* out = (float*)d_out;

    se_pool_kernel<<<NPLANES, 256>>>(trans_b);
    se_mlp_kernel<<<32, 64>>>(w_down, b_down, w_up, b_up);
    se_scale_kernel<<<TOTAL_F4 / 1024, 256>>>(trans_b, out);
}